// round 3
// baseline (speedup 1.0000x reference)
#include <cuda_runtime.h>
#include <cstdint>

// Problem constants
#define T_TOK 2048
#define D_DIM 2048
#define N_OUT 11264
#define L_N   16
#define R_N   16
#define BD    5632   // half of 2*BDIM

// GEMM tiling
#define BM 128
#define BN 128
#define BK 8
#define TM 8
#define TN 8
#define NTHREADS 256

// Scratch: xa[t][32] = einsum('d,dr->r', x[t], A_buffer[idx[t]])  (both halves)
__device__ float g_xa[T_TOK * 32];

// ---------------------------------------------------------------------------
// Kernel 1: per-token xa = x[t,:] @ A_buffer[l_t]   (2048 x 2048 x 32)
// grid = T_TOK blocks, 256 threads. Thread (chunk,r): chunk = tid/32 covers a
// 256-wide d-slice, r = tid%32 is the output column. A loads are coalesced
// (lanes r consecutive), x loads broadcast.
// NOTE: weight_indices is int32 on device (JAX demotes int64 without x64).
// ---------------------------------------------------------------------------
__global__ void xa_kernel(const float* __restrict__ x,
                          const float* __restrict__ A,
                          const int* __restrict__ idx) {
    int t = blockIdx.x;
    int l = idx[t];
    const float* __restrict__ Ab = A + (size_t)l * (size_t)D_DIM * 32;
    const float* __restrict__ xr = x + (size_t)t * D_DIM;

    int r     = threadIdx.x & 31;
    int chunk = threadIdx.x >> 5;          // 0..7
    int d0    = chunk * (D_DIM / 8);

    float acc = 0.f;
#pragma unroll 8
    for (int d = d0; d < d0 + D_DIM / 8; ++d)
        acc = fmaf(xr[d], Ab[(size_t)d * 32 + r], acc);

    __shared__ float red[8][32];
    red[chunk][r] = acc;
    __syncthreads();
    if (chunk == 0) {
        float s = red[0][r];
#pragma unroll
        for (int c = 1; c < 8; ++c) s += red[c][r];
        g_xa[t * 32 + r] = s;
    }
}

// ---------------------------------------------------------------------------
// Kernel 2: fused GEMM + LoRA delta.
// out[t,n] = sum_d x[t,d]*W[n,d]  +  sum_r xa[t, 16*half+r] * Bbuf[l_t, r, n]
// 128x128 tile, K=8 steps, 256 threads, 8x8 microtile, double-buffered smem.
// Both x and W are K-major (row-major with K contiguous) -> float4 loads.
// ---------------------------------------------------------------------------
__global__ __launch_bounds__(NTHREADS, 2)
void gemm_delta_kernel(const float* __restrict__ x,
                       const float* __restrict__ W,
                       const float* __restrict__ Bbuf,
                       const int* __restrict__ idx,
                       float* __restrict__ out) {
    __shared__ float As[2][BK][BM];
    __shared__ float Bs[2][BK][BN];
    __shared__ float xa_s[BM][16];
    __shared__ int   ls[BM];

    const int tid = threadIdx.x;
    const int bm  = blockIdx.y * BM;     // token tile
    const int bn  = blockIdx.x * BN;     // output-col tile (never straddles BD)

    // ---- preload per-tile delta metadata into smem ----
    const int half = (bn >= BD) ? 1 : 0;
    for (int i = tid; i < BM * 16; i += NTHREADS) {
        int row = i >> 4, r = i & 15;
        xa_s[row][r] = g_xa[(bm + row) * 32 + half * 16 + r];
    }
    if (tid < BM) ls[tid] = idx[bm + tid];

    // ---- global load mapping: 2 threads per row, each a float4 along K ----
    const int lrow = tid >> 1;            // 0..127
    const int lk   = (tid & 1) * 4;       // 0 or 4
    const float* __restrict__ Ag = x + (size_t)(bm + lrow) * D_DIM + lk;
    const float* __restrict__ Bg = W + (size_t)(bn + lrow) * D_DIM + lk;

    float c[TM][TN];
#pragma unroll
    for (int i = 0; i < TM; ++i)
#pragma unroll
        for (int j = 0; j < TN; ++j) c[i][j] = 0.f;

    // prefetch k=0
    float4 a4 = *(const float4*)(Ag);
    float4 b4 = *(const float4*)(Bg);
    As[0][lk + 0][lrow] = a4.x; As[0][lk + 1][lrow] = a4.y;
    As[0][lk + 2][lrow] = a4.z; As[0][lk + 3][lrow] = a4.w;
    Bs[0][lk + 0][lrow] = b4.x; Bs[0][lk + 1][lrow] = b4.y;
    Bs[0][lk + 2][lrow] = b4.z; Bs[0][lk + 3][lrow] = b4.w;
    __syncthreads();

    const int ty = tid >> 4;              // 0..15 -> rows ty*8..ty*8+7
    const int tx = tid & 15;              // 0..15 -> cols tx*8..tx*8+7
    int buf = 0;

    for (int k = BK; k <= D_DIM; k += BK) {
        if (k < D_DIM) {
            a4 = *(const float4*)(Ag + k);
            b4 = *(const float4*)(Bg + k);
        }
#pragma unroll
        for (int kk = 0; kk < BK; ++kk) {
            float4 av0 = *(const float4*)(&As[buf][kk][ty * TM]);
            float4 av1 = *(const float4*)(&As[buf][kk][ty * TM + 4]);
            float4 bv0 = *(const float4*)(&Bs[buf][kk][tx * TN]);
            float4 bv1 = *(const float4*)(&Bs[buf][kk][tx * TN + 4]);
            float a[TM] = {av0.x, av0.y, av0.z, av0.w, av1.x, av1.y, av1.z, av1.w};
            float b[TN] = {bv0.x, bv0.y, bv0.z, bv0.w, bv1.x, bv1.y, bv1.z, bv1.w};
#pragma unroll
            for (int i = 0; i < TM; ++i)
#pragma unroll
                for (int j = 0; j < TN; ++j)
                    c[i][j] = fmaf(a[i], b[j], c[i][j]);
        }
        if (k < D_DIM) {
            buf ^= 1;
            As[buf][lk + 0][lrow] = a4.x; As[buf][lk + 1][lrow] = a4.y;
            As[buf][lk + 2][lrow] = a4.z; As[buf][lk + 3][lrow] = a4.w;
            Bs[buf][lk + 0][lrow] = b4.x; Bs[buf][lk + 1][lrow] = b4.y;
            Bs[buf][lk + 2][lrow] = b4.z; Bs[buf][lk + 3][lrow] = b4.w;
            __syncthreads();
        }
    }

    // ---- epilogue: fused LoRA delta + store ----
    // delta c[i][j] += sum_r xa_s[row][r] * Bbuf[l, r, n_global]
    const int ncol0 = bn + tx * TN;       // global first col of this thread
#pragma unroll
    for (int i = 0; i < TM; ++i) {
        const int row = ty * TM + i;
        const int l = ls[row];
        const float* __restrict__ Bp =
            Bbuf + ((size_t)l * R_N) * (2 * BD) + ncol0;
#pragma unroll
        for (int r = 0; r < R_N; ++r) {
            float xav = xa_s[row][r];
            const float* __restrict__ Bpr = Bp + (size_t)r * (2 * BD);
            float4 b0 = *(const float4*)(Bpr);
            float4 b1 = *(const float4*)(Bpr + 4);
            c[i][0] = fmaf(xav, b0.x, c[i][0]);
            c[i][1] = fmaf(xav, b0.y, c[i][1]);
            c[i][2] = fmaf(xav, b0.z, c[i][2]);
            c[i][3] = fmaf(xav, b0.w, c[i][3]);
            c[i][4] = fmaf(xav, b1.x, c[i][4]);
            c[i][5] = fmaf(xav, b1.y, c[i][5]);
            c[i][6] = fmaf(xav, b1.z, c[i][6]);
            c[i][7] = fmaf(xav, b1.w, c[i][7]);
        }
        float* __restrict__ op = out + (size_t)(bm + row) * N_OUT + ncol0;
        float4 o0 = make_float4(c[i][0], c[i][1], c[i][2], c[i][3]);
        float4 o1 = make_float4(c[i][4], c[i][5], c[i][6], c[i][7]);
        *(float4*)(op)     = o0;
        *(float4*)(op + 4) = o1;
    }
}

// ---------------------------------------------------------------------------
// Inputs (metadata order): x[T,D] f32, W[2*BD,D] f32, A_buffer[L,D,2R] f32,
// B_buffer[L,R,2*BD] f32, weight_indices[T] int32. Output: f32 [T, 2*BD].
// ---------------------------------------------------------------------------
extern "C" void kernel_launch(void* const* d_in, const int* in_sizes, int n_in,
                              void* d_out, int out_size) {
    const float* x    = (const float*)d_in[0];
    const float* W    = (const float*)d_in[1];
    const float* Abuf = (const float*)d_in[2];
    const float* Bbuf = (const float*)d_in[3];
    const int*   idx  = (const int*)d_in[4];
    float*       out  = (float*)d_out;

    xa_kernel<<<T_TOK, 256>>>(x, Abuf, idx);

    dim3 grid(N_OUT / BN, T_TOK / BM);   // 88 x 16
    gemm_delta_kernel<<<grid, NTHREADS>>>(x, W, Bbuf, idx, out);
}

// round 5
// speedup vs baseline: 3.7884x; 3.7884x over previous
#include <cuda_runtime.h>
#include <cstdint>

// ---------------- problem constants ----------------
#define T_TOK 2048
#define D_DIM 2048
#define N_OUT 11264
#define R_N   16
#define BD    5632

// ---------------- GEMM config ----------------
#define BM 128
#define BN 128
#define BK 32                  // K per stage (32 f32 = 128B row)
#define NST 4                  // cp.async pipeline stages
#define NSTEP (D_DIM / BK)     // 64
#define NTHREADS 256

// smem layout (byte offsets into dynamic smem)
#define OFF_LS   0             // 128 ints
#define OFF_XA   512           // 128*16 floats = 8192
#define OFF_PIPE 9216          // NST * 32768 (A 16K + B 16K per stage)
#define STAGE_BYTES 32768
#define SMEM_BYTES (OFF_PIPE + NST * STAGE_BYTES)   // 140288

__device__ float g_xa[T_TOK * 32];

// ---------------- helpers ----------------
__device__ __forceinline__ uint32_t smem_u32(const void* p) {
    uint32_t a;
    asm("{ .reg .u64 t; cvta.to.shared.u64 t, %1; cvt.u32.u64 %0, t; }" : "=r"(a) : "l"(p));
    return a;
}
#define CP_ASYNC16(dst, src) \
    asm volatile("cp.async.cg.shared.global [%0], [%1], 16;" :: "r"(dst), "l"(src) : "memory")
#define CP_COMMIT() asm volatile("cp.async.commit_group;" ::: "memory")
#define CP_WAIT2()  asm volatile("cp.async.wait_group 2;" ::: "memory")

__device__ __forceinline__ uint32_t swz(uint32_t off) { return off ^ ((off >> 3) & 0x70); }

__device__ __forceinline__ float lds_swz(const char* p, uint32_t off) {
    return *reinterpret_cast<const float*>(p + (off ^ ((off >> 3) & 0x70)));
}
__device__ __forceinline__ uint32_t f2tf(float f) {
    uint32_t u; asm("cvt.rna.tf32.f32 %0, %1;" : "=r"(u) : "f"(f)); return u;
}
__device__ __forceinline__ void mma_tf32(float* c, const uint32_t* a, const uint32_t* b) {
    asm volatile("mma.sync.aligned.m16n8k8.row.col.f32.tf32.tf32.f32 "
        "{%0,%1,%2,%3}, {%4,%5,%6,%7}, {%8,%9}, {%0,%1,%2,%3};"
        : "+f"(c[0]), "+f"(c[1]), "+f"(c[2]), "+f"(c[3])
        : "r"(a[0]), "r"(a[1]), "r"(a[2]), "r"(a[3]), "r"(b[0]), "r"(b[1]));
}

// ---------------------------------------------------------------------------
// Kernel 1: xa[t, 0..31] = x[t,:] @ A_buffer[idx[t]]  (fp32, float4 loads)
// ---------------------------------------------------------------------------
__global__ void xa_kernel(const float* __restrict__ x,
                          const float* __restrict__ A,
                          const int* __restrict__ idx) {
    __shared__ float xs[D_DIM];
    __shared__ float red[32][36];

    const int t = blockIdx.x;
    const int l = idx[t];
    const int tid = threadIdx.x;

    const float4* xr4 = (const float4*)(x + (size_t)t * D_DIM);
#pragma unroll
    for (int i = 0; i < 2; ++i)
        ((float4*)xs)[tid + i * 256] = xr4[tid + i * 256];
    __syncthreads();

    const int rq = tid & 7;        // r-quad: cols rq*4..rq*4+3
    const int slice = tid >> 3;    // 32 slices of 64 d each
    const float4* A4 = (const float4*)(A + (size_t)l * D_DIM * 32);

    float4 acc = make_float4(0.f, 0.f, 0.f, 0.f);
#pragma unroll 4
    for (int i = 0; i < 64; ++i) {
        int d = slice * 64 + i;
        float4 a = A4[(size_t)d * 8 + rq];
        float xv = xs[d];
        acc.x = fmaf(xv, a.x, acc.x);
        acc.y = fmaf(xv, a.y, acc.y);
        acc.z = fmaf(xv, a.z, acc.z);
        acc.w = fmaf(xv, a.w, acc.w);
    }
    red[slice][rq * 4 + 0] = acc.x;
    red[slice][rq * 4 + 1] = acc.y;
    red[slice][rq * 4 + 2] = acc.z;
    red[slice][rq * 4 + 3] = acc.w;
    __syncthreads();

    if (tid < 32) {
        float s = 0.f;
#pragma unroll
        for (int k = 0; k < 32; ++k) s += red[k][tid];
        g_xa[t * 32 + tid] = s;
    }
}

// ---------------------------------------------------------------------------
// Kernel 2: tf32 mma.sync GEMM (128x128 tile) + fused LoRA-delta epilogue
// ---------------------------------------------------------------------------
__device__ __forceinline__ void load_stage(uint32_t saA, uint32_t saB,
                                           const float* __restrict__ xg,
                                           const float* __restrict__ wg, int tid) {
#pragma unroll
    for (int i = 0; i < 4; ++i) {
        int idx = tid + i * 256;
        int row = idx >> 3, seg = idx & 7;
        CP_ASYNC16(saA + swz(row * 128 + seg * 16), xg + (size_t)row * D_DIM + seg * 4);
    }
#pragma unroll
    for (int i = 0; i < 4; ++i) {
        int idx = tid + i * 256;
        int row = idx >> 3, seg = idx & 7;
        CP_ASYNC16(saB + swz(row * 128 + seg * 16), wg + (size_t)row * D_DIM + seg * 4);
    }
}

__global__ __launch_bounds__(NTHREADS, 1)
void gemm_tc_kernel(const float* __restrict__ x,
                    const float* __restrict__ W,
                    const float* __restrict__ Bbuf,
                    const int* __restrict__ idx,
                    float* __restrict__ out) {
    extern __shared__ char sm[];
    const uint32_t sb = smem_u32(sm);

    const int tid = threadIdx.x;
    const int wid = tid >> 5, lane = tid & 31;
    const int wm = wid & 3;        // 4 warp-rows of 32
    const int wn = wid >> 2;       // 2 warp-cols of 64
    const int bm = blockIdx.y * BM;
    const int bn = blockIdx.x * BN;

    float* xa_s = (float*)(sm + OFF_XA);
    int*   ls   = (int*)(sm + OFF_LS);

    // delta metadata
    const int half = (bn >= BD) ? 1 : 0;
    for (int i = tid; i < BM * 16; i += NTHREADS) {
        int row = i >> 4, r = i & 15;
        xa_s[row * 16 + r] = g_xa[(bm + row) * 32 + half * 16 + r];
    }
    if (tid < BM) ls[tid] = idx[bm + tid];

    const float* xbase = x + (size_t)bm * D_DIM;
    const float* wbase = W + (size_t)bn * D_DIM;

    // prologue: stages 0..2
#pragma unroll
    for (int s = 0; s < NST - 1; ++s) {
        load_stage(sb + OFF_PIPE + s * STAGE_BYTES,
                   sb + OFF_PIPE + s * STAGE_BYTES + 16384,
                   xbase + s * BK, wbase + s * BK, tid);
        CP_COMMIT();
    }

    float acc[2][8][4];
#pragma unroll
    for (int mt = 0; mt < 2; ++mt)
#pragma unroll
        for (int nt = 0; nt < 8; ++nt)
#pragma unroll
            for (int j = 0; j < 4; ++j) acc[mt][nt][j] = 0.f;

    const int mrow = (lane >> 2);    // 0..7
    const int kcol = (lane & 3);     // 0..3

    for (int s = 0; s < NSTEP; ++s) {
        CP_WAIT2();
        __syncthreads();

        if (s + NST - 1 < NSTEP) {
            int slot = (s + NST - 1) & (NST - 1);
            load_stage(sb + OFF_PIPE + slot * STAGE_BYTES,
                       sb + OFF_PIPE + slot * STAGE_BYTES + 16384,
                       xbase + (s + NST - 1) * BK, wbase + (s + NST - 1) * BK, tid);
        }
        CP_COMMIT();

        const char* As = sm + OFF_PIPE + (s & (NST - 1)) * STAGE_BYTES;
        const char* Bs = As + 16384;

#pragma unroll
        for (int kk = 0; kk < 4; ++kk) {
            const uint32_t k0 = kk * 8 + kcol;
            uint32_t a[2][4];
#pragma unroll
            for (int mt = 0; mt < 2; ++mt) {
                uint32_t m0 = wm * 32 + mt * 16 + mrow;
                a[mt][0] = f2tf(lds_swz(As, m0 * 128 + k0 * 4));
                a[mt][1] = f2tf(lds_swz(As, (m0 + 8) * 128 + k0 * 4));
                a[mt][2] = f2tf(lds_swz(As, m0 * 128 + (k0 + 4) * 4));
                a[mt][3] = f2tf(lds_swz(As, (m0 + 8) * 128 + (k0 + 4) * 4));
            }
            uint32_t b[8][2];
#pragma unroll
            for (int nt = 0; nt < 8; ++nt) {
                uint32_t n0 = wn * 64 + nt * 8 + mrow;
                b[nt][0] = f2tf(lds_swz(Bs, n0 * 128 + k0 * 4));
                b[nt][1] = f2tf(lds_swz(Bs, n0 * 128 + (k0 + 4) * 4));
            }
#pragma unroll
            for (int mt = 0; mt < 2; ++mt)
#pragma unroll
                for (int nt = 0; nt < 8; ++nt)
                    mma_tf32(acc[mt][nt], a[mt], b[nt]);
        }
    }

    // ---- stage accumulators to smem (reuse pipeline region), padded rows ----
    __syncthreads();
    float* Cs = (float*)(sm + OFF_PIPE);
#pragma unroll
    for (int mt = 0; mt < 2; ++mt)
#pragma unroll
        for (int nt = 0; nt < 8; ++nt) {
            int row0 = wm * 32 + mt * 16 + mrow;
            int col  = wn * 64 + nt * 8 + kcol * 2;
            *(float2*)&Cs[row0 * 132 + col]       = make_float2(acc[mt][nt][0], acc[mt][nt][1]);
            *(float2*)&Cs[(row0 + 8) * 132 + col] = make_float2(acc[mt][nt][2], acc[mt][nt][3]);
        }
    __syncthreads();

    // ---- epilogue: thread -> (row = tid>>1, 64-col half), fused LoRA delta ----
    {
        const int row = tid >> 1;
        const int ch  = (tid & 1) * 64;
        const int l   = ls[row];

        float v[64];
#pragma unroll
        for (int j = 0; j < 16; ++j) {
            float4 t4 = *(const float4*)&Cs[row * 132 + ch + 4 * j];
            v[4 * j] = t4.x; v[4 * j + 1] = t4.y; v[4 * j + 2] = t4.z; v[4 * j + 3] = t4.w;
        }
        const float* xav = &xa_s[row * 16];
        const float* Bp = Bbuf + (size_t)l * 16 * N_OUT + bn + ch;
#pragma unroll
        for (int r = 0; r < R_N; ++r) {
            float xv = xav[r];
            const float4* B4 = (const float4*)(Bp + (size_t)r * N_OUT);
#pragma unroll
            for (int j = 0; j < 16; ++j) {
                float4 bb = B4[j];
                v[4 * j + 0] = fmaf(xv, bb.x, v[4 * j + 0]);
                v[4 * j + 1] = fmaf(xv, bb.y, v[4 * j + 1]);
                v[4 * j + 2] = fmaf(xv, bb.z, v[4 * j + 2]);
                v[4 * j + 3] = fmaf(xv, bb.w, v[4 * j + 3]);
            }
        }
        float* op = out + (size_t)(bm + row) * N_OUT + bn + ch;
#pragma unroll
        for (int j = 0; j < 16; ++j)
            ((float4*)op)[j] = make_float4(v[4 * j], v[4 * j + 1], v[4 * j + 2], v[4 * j + 3]);
    }
}

// ---------------------------------------------------------------------------
extern "C" void kernel_launch(void* const* d_in, const int* in_sizes, int n_in,
                              void* d_out, int out_size) {
    const float* x    = (const float*)d_in[0];
    const float* W    = (const float*)d_in[1];
    const float* Abuf = (const float*)d_in[2];
    const float* Bbuf = (const float*)d_in[3];
    const int*   idx  = (const int*)d_in[4];
    float*       out  = (float*)d_out;

    cudaFuncSetAttribute(gemm_tc_kernel,
                         cudaFuncAttributeMaxDynamicSharedMemorySize, SMEM_BYTES);

    xa_kernel<<<T_TOK, 256>>>(x, Abuf, idx);

    dim3 grid(N_OUT / BN, T_TOK / BM);   // 88 x 16
    gemm_tc_kernel<<<grid, NTHREADS, SMEM_BYTES>>>(x, W, Bbuf, idx, out);
}